// round 7
// baseline (speedup 1.0000x reference)
#include <cuda_runtime.h>
#include <math.h>
#include <stdint.h>

#define NB 4
#define NS 2048
#define ND 1024
#define NH 16
#define HDIM 64
#define NM (NB*NS)   // 8192 rows
#define MM (ND*ND)

// Scratch (allocation-free rule: __device__ globals). ~182 MB total.
// g_Q: [bh][s][d]            (natural fp32)
// g_K: [bh][d][key]          key permuted per 64-block: pos=(k&7)*8+((k>>3)&7); tf32
// g_V: [bh][key][d']         d' = (d&7)*8 + (d>>3); tf32
// g_AO: attention out [B,S,D], tf32-rounded
// g_XP: tf32-rounded copy of x;  g_WP: tf32-rounded copies of Wq,Wk,Wv,Wo
__device__ __align__(256) float g_Q[(size_t)NB*NH*NS*HDIM];
__device__ __align__(256) float g_K[(size_t)NB*NH*NS*HDIM];
__device__ __align__(256) float g_V[(size_t)NB*NH*NS*HDIM];
__device__ __align__(256) float g_AO[(size_t)NB*NS*ND];
__device__ __align__(256) float g_XP[(size_t)NM*ND];
__device__ __align__(256) float g_WP[(size_t)4*MM];

__device__ __forceinline__ float to_tf32(float x) {
    float r;
    asm("cvt.rna.tf32.f32 %0, %1;" : "=f"(r) : "f"(x));
    return r;
}

__device__ __forceinline__ void mma_tf32(float d[4], const uint32_t a[4],
                                         const uint32_t b[2]) {
    asm volatile(
        "mma.sync.aligned.m16n8k8.row.col.f32.tf32.tf32.f32 "
        "{%0,%1,%2,%3},{%4,%5,%6,%7},{%8,%9},{%0,%1,%2,%3};"
        : "+f"(d[0]), "+f"(d[1]), "+f"(d[2]), "+f"(d[3])
        : "r"(a[0]), "r"(a[1]), "r"(a[2]), "r"(a[3]),
          "r"(b[0]), "r"(b[1]));
}

__device__ __forceinline__ void cp16(void* dst, const void* src) {
    uint32_t d = (uint32_t)__cvta_generic_to_shared(dst);
    asm volatile("cp.async.cg.shared.global [%0], [%1], 16;" :: "r"(d), "l"(src));
}
__device__ __forceinline__ void cp_commit() {
    asm volatile("cp.async.commit_group;" ::: "memory");
}
__device__ __forceinline__ void cp_wait0() {
    asm volatile("cp.async.wait_group 0;" ::: "memory");
}
__device__ __forceinline__ void cp_wait1() {
    asm volatile("cp.async.wait_group 1;" ::: "memory");
}

// ---------------------------------------------------------------------------
// Prep: round x and the 4 weight matrices to tf32 (RNA) into scratch.
// ---------------------------------------------------------------------------
__global__ __launch_bounds__(256) void prep_round(
    const float* __restrict__ x,
    const float* __restrict__ wq, const float* __restrict__ wk,
    const float* __restrict__ wv, const float* __restrict__ wo)
{
    const size_t XQ = (size_t)NM * ND / 4;
    const size_t WQ = (size_t)MM / 4;
    size_t i = (size_t)blockIdx.x * 256 + threadIdx.x;
    if (i < XQ) {
        float4 v = ((const float4*)x)[i];
        v.x = to_tf32(v.x); v.y = to_tf32(v.y);
        v.z = to_tf32(v.z); v.w = to_tf32(v.w);
        ((float4*)g_XP)[i] = v;
    } else if (i < XQ + 4 * WQ) {
        size_t j = i - XQ;
        int w = (int)(j / WQ);
        size_t o = j - (size_t)w * WQ;
        const float* src = (w == 0) ? wq : (w == 1) ? wk : (w == 2) ? wv : wo;
        float4 v = ((const float4*)src)[o];
        v.x = to_tf32(v.x); v.y = to_tf32(v.y);
        v.z = to_tf32(v.z); v.w = to_tf32(v.w);
        ((float4*)g_WP)[j] = v;
    }
}

// ---------------------------------------------------------------------------
// C = A @ W^T + bias, TF32 mma.sync.  A:[M,K] rm (pre-rounded), W from g_WP.
// CTA 128x128x32, 4 warps (2m x 2n), warp 64x64.
// 3-stage cp.async ring, ONE barrier per K-chunk, loads for c+2 issued
// before compute(c).
// ---------------------------------------------------------------------------
#define SSg 36
#define GSTF (128*SSg)               // floats per A (or B) block: 4608
#define STAGEF (2*GSTF)              // floats per stage: 9216
#define GEMM_SMEM (3*STAGEF*4)       // 110592 B

__global__ __launch_bounds__(128, 2) void gemm_tf32(
    const float* __restrict__ b0, const float* __restrict__ b1,
    const float* __restrict__ b2, float* __restrict__ Cout,
    int amode, int fused, int cmode0)
{
    extern __shared__ float smg[];

    const float* A = amode ? g_AO : g_XP;
    int sel, nblk, cmode;
    const float* bias;
    if (fused) {
        sel  = blockIdx.x >> 3;
        nblk = blockIdx.x & 7;
        bias = (sel == 0) ? b0 : (sel == 1) ? b1 : b2;
        cmode = sel + 1;
    } else {
        sel = 3; nblk = blockIdx.x;
        bias = b0; cmode = cmode0;
    }
    const float* W = g_WP + (size_t)sel * MM;

    const int tid  = threadIdx.x;
    const int lane = tid & 31;
    const int wid  = tid >> 5;
    const int wm   = wid & 1;
    const int wn   = wid >> 1;
    const int m0   = blockIdx.y * 128;
    const int n0   = nblk * 128;
    const int g    = lane >> 2;
    const int tig  = lane & 3;

    float acc[4][8][4];
#pragma unroll
    for (int i = 0; i < 4; i++)
#pragma unroll
        for (int j = 0; j < 8; j++)
#pragma unroll
            for (int c = 0; c < 4; c++) acc[i][j][c] = 0.0f;

    const float* Ap = A + (size_t)m0 * ND;
    const float* Wp = W + (size_t)n0 * ND;

    auto loadStage = [&](int c) {
        float* As = smg + (c % 3) * STAGEF;
        float* Bs = As + GSTF;
#pragma unroll
        for (int i = 0; i < 8; i++) {
            int f = tid + i * 128;          // 0..1023
            int row = f >> 3, q = f & 7;
            cp16(&As[row * SSg + q * 4], Ap + (size_t)row * ND + c * 32 + q * 4);
            cp16(&Bs[row * SSg + q * 4], Wp + (size_t)row * ND + c * 32 + q * 4);
        }
    };

    constexpr int NCH = ND / 32;   // 32
    loadStage(0); cp_commit();
    loadStage(1); cp_commit();

    for (int c = 0; c < NCH; c++) {
        if (c + 1 < NCH) cp_wait1(); else cp_wait0();
        __syncthreads();
        if (c + 2 < NCH) { loadStage(c + 2); cp_commit(); }

        const float* As = smg + (c % 3) * STAGEF;
        const float* Bs = As + GSTF;

#pragma unroll
        for (int s = 0; s < 4; s++) {
            uint32_t af[4][4];
#pragma unroll
            for (int mi = 0; mi < 4; mi++) {
                int r = wm * 64 + mi * 16 + g;
                const float* p0 = &As[r * SSg + 8 * s + tig];
                const float* p1 = &As[(r + 8) * SSg + 8 * s + tig];
                af[mi][0] = __float_as_uint(p0[0]);
                af[mi][1] = __float_as_uint(p1[0]);
                af[mi][2] = __float_as_uint(p0[4]);
                af[mi][3] = __float_as_uint(p1[4]);
            }
            uint32_t bf[8][2];
#pragma unroll
            for (int ni = 0; ni < 8; ni++) {
                const float* p = &Bs[(wn * 64 + ni * 8 + g) * SSg + 8 * s + tig];
                bf[ni][0] = __float_as_uint(p[0]);
                bf[ni][1] = __float_as_uint(p[4]);
            }
#pragma unroll
            for (int mi = 0; mi < 4; mi++)
#pragma unroll
                for (int ni = 0; ni < 8; ni++)
                    mma_tf32(acc[mi][ni], af[mi], bf[ni]);
        }
        // no trailing barrier: stage (c%3) is not re-targeted until iter c+1's
        // barrier has passed (loads for c+3 happen after it)
    }

    // ---- epilogue ----
#pragma unroll
    for (int mi = 0; mi < 4; mi++) {
#pragma unroll
        for (int ni = 0; ni < 8; ni++) {
#pragma unroll
            for (int c = 0; c < 4; c++) {
                int m = m0 + wm * 64 + mi * 16 + g + (c >> 1) * 8;
                int n = n0 + wn * 64 + ni * 8 + tig * 2 + (c & 1);
                float v = acc[mi][ni][c] + bias[n];
                if (cmode == 0) {
                    Cout[(size_t)m * ND + n] = v;
                } else {
                    int bb = m >> 11, ss = m & 2047;
                    int h = n >> 6, hd = n & 63;
                    if (cmode == 1) {
                        g_Q[(((size_t)(bb * NH + h)) * NS + ss) * HDIM + hd] = v;
                    } else if (cmode == 2) {
                        size_t off = (((size_t)(bb * NH + h)) * HDIM + hd) * NS
                                   + (ss & ~63) + ((ss & 7) * 8 + ((ss >> 3) & 7));
                        g_K[off] = to_tf32(v);
                    } else {
                        size_t off = (((size_t)(bb * NH + h)) * NS + ss) * HDIM
                                   + ((hd & 7) * 8 + (hd >> 3));
                        g_V[off] = to_tf32(v);
                    }
                }
            }
        }
    }
}

// ---------------------------------------------------------------------------
// Tensor-core flash attention, tf32 mma, causal.  (unchanged from R6)
// CTA: 128 q-rows of one (b,h); 4 warps, each owns m16 tiles {wq, 7-wq}.
// ---------------------------------------------------------------------------
#define KSS 68
#define QROWS 128
#define FLASH_SMEM ((4*64*KSS + QROWS*KSS) * 4)   // 104448 B

__global__ __launch_bounds__(128, 2) void flash_attn_mma()
{
    extern __shared__ float sm[];
    float* KsA[2] = { sm,            sm + 64*KSS };
    float* VsA[2] = { sm + 2*64*KSS, sm + 3*64*KSS };
    float* Ps     = sm + 4*64*KSS;

    const int tid  = threadIdx.x;
    const int lane = tid & 31;
    const int wq   = tid >> 5;
    const int g    = lane >> 2;
    const int tig  = lane & 3;
    const int bh   = blockIdx.y;
    const int qt   = (int)gridDim.x - 1 - (int)blockIdx.x;
    const int q0   = qt * QROWS;

    const int tt[2]   = { wq, 7 - wq };
    const int trow[2] = { q0 + tt[0] * 16, q0 + tt[1] * 16 };

    const float* Qb = g_Q + (size_t)bh * NS * HDIM;
    const float* Kb = g_K + (size_t)bh * HDIM * NS;
    const float* Vb = g_V + (size_t)bh * NS * HDIM;

#pragma unroll
    for (int i = 0; i < 16; i++) {
        int f4 = tid + i * 128;
        int row = f4 >> 4, c = (f4 & 15) * 4;
        *(float4*)&Ps[row * KSS + c] =
            *(const float4*)(Qb + (size_t)(q0 + row) * HDIM + c);
    }
    __syncthreads();

    float qf[2][8][4];
#pragma unroll
    for (int mi = 0; mi < 2; mi++) {
        const float* Q0 = &Ps[(tt[mi] * 16 + g) * KSS];
        const float* Q1 = &Ps[(tt[mi] * 16 + g + 8) * KSS];
#pragma unroll
        for (int s = 0; s < 8; s++) {
            qf[mi][s][0] = to_tf32(Q0[8 * s + tig] * 0.125f);
            qf[mi][s][1] = to_tf32(Q1[8 * s + tig] * 0.125f);
            qf[mi][s][2] = to_tf32(Q0[8 * s + tig + 4] * 0.125f);
            qf[mi][s][3] = to_tf32(Q1[8 * s + tig + 4] * 0.125f);
        }
    }
    __syncthreads();

    const int ktmax = 2 * qt + 1;

    auto prefetch = [&](int t) {
        float* kd = KsA[t & 1];
        float* vd = VsA[t & 1];
        int kk0 = t * 64;
#pragma unroll
        for (int i = 0; i < 8; i++) {
            int f4 = tid + i * 128;
            int row = f4 >> 4, c = (f4 & 15) * 4;
            cp16(&kd[row * KSS + c], Kb + (size_t)row * NS + kk0 + c);
            cp16(&vd[row * KSS + c], Vb + (size_t)(kk0 + row) * HDIM + c);
        }
    };

    prefetch(0);
    cp_commit();

    float oacc[2][8][4];
#pragma unroll
    for (int mi = 0; mi < 2; mi++)
#pragma unroll
        for (int i = 0; i < 8; i++)
#pragma unroll
            for (int c = 0; c < 4; c++) oacc[mi][i][c] = 0.0f;
    float mx[2][2] = { {-INFINITY, -INFINITY}, {-INFINITY, -INFINITY} };
    float ls[2][2] = { {0.0f, 0.0f}, {0.0f, 0.0f} };
    float* Pw = Ps + (wq * 32) * KSS;

    for (int kt = 0; kt <= ktmax; kt++) {
        cp_wait0();
        __syncthreads();
        if (kt < ktmax) { prefetch(kt + 1); cp_commit(); }

        const int k0 = kt * 64;
        const bool act0 = (k0 <= trow[0] + 15);
        const bool act1 = (k0 <= trow[1] + 15);
        if (act1) {
            const float* K = KsA[kt & 1];
            const float* V = VsA[kt & 1];

            float sacc[2][8][4];
#pragma unroll
            for (int mi = 0; mi < 2; mi++)
#pragma unroll
                for (int i = 0; i < 8; i++)
#pragma unroll
                    for (int c = 0; c < 4; c++) sacc[mi][i][c] = 0.0f;

#pragma unroll
            for (int s = 0; s < 8; s++) {
                float k0a[8], k1a[8];
                const float* kr0 = &K[(8 * s + tig) * KSS + 8 * g];
                const float* kr1 = &K[(8 * s + tig + 4) * KSS + 8 * g];
                *(float4*)&k0a[0] = *(const float4*)&kr0[0];
                *(float4*)&k0a[4] = *(const float4*)&kr0[4];
                *(float4*)&k1a[0] = *(const float4*)&kr1[0];
                *(float4*)&k1a[4] = *(const float4*)&kr1[4];
#pragma unroll
                for (int mi = 0; mi < 2; mi++) {
                    if (mi == 0 && !act0) continue;
                    uint32_t a[4] = { __float_as_uint(qf[mi][s][0]),
                                      __float_as_uint(qf[mi][s][1]),
                                      __float_as_uint(qf[mi][s][2]),
                                      __float_as_uint(qf[mi][s][3]) };
#pragma unroll
                    for (int nt = 0; nt < 8; nt++) {
                        uint32_t b[2] = { __float_as_uint(k0a[nt]),
                                          __float_as_uint(k1a[nt]) };
                        mma_tf32(sacc[mi][nt], a, b);
                    }
                }
            }

#pragma unroll
            for (int mi = 0; mi < 2; mi++) {
                if (mi == 0 && !act0) continue;
                if (k0 + 63 > trow[mi]) {
                    int r0 = trow[mi] + g, r1 = r0 + 8;
#pragma unroll
                    for (int nt = 0; nt < 8; nt++) {
                        int c0 = k0 + 8 * nt + 2 * tig;
                        if (c0     > r0) sacc[mi][nt][0] = -INFINITY;
                        if (c0 + 1 > r0) sacc[mi][nt][1] = -INFINITY;
                        if (c0     > r1) sacc[mi][nt][2] = -INFINITY;
                        if (c0 + 1 > r1) sacc[mi][nt][3] = -INFINITY;
                    }
                }
            }

#pragma unroll
            for (int mi = 0; mi < 2; mi++) {
                if (mi == 0 && !act0) continue;
                float t0 = -INFINITY, t1 = -INFINITY;
#pragma unroll
                for (int nt = 0; nt < 8; nt++) {
                    t0 = fmaxf(t0, fmaxf(sacc[mi][nt][0], sacc[mi][nt][1]));
                    t1 = fmaxf(t1, fmaxf(sacc[mi][nt][2], sacc[mi][nt][3]));
                }
                t0 = fmaxf(t0, __shfl_xor_sync(0xffffffffu, t0, 1));
                t0 = fmaxf(t0, __shfl_xor_sync(0xffffffffu, t0, 2));
                t1 = fmaxf(t1, __shfl_xor_sync(0xffffffffu, t1, 1));
                t1 = fmaxf(t1, __shfl_xor_sync(0xffffffffu, t1, 2));
                float nm0 = fmaxf(mx[mi][0], t0), nm1 = fmaxf(mx[mi][1], t1);
                float corr0 = __expf(mx[mi][0] - nm0);
                float corr1 = __expf(mx[mi][1] - nm1);

                float* P0 = &Pw[(mi * 16 + g) * KSS];
                float* P1 = &Pw[(mi * 16 + g + 8) * KSS];
                float ps0 = 0.0f, ps1 = 0.0f;
#pragma unroll
                for (int nt = 0; nt < 8; nt++) {
                    float p0 = __expf(sacc[mi][nt][0] - nm0);
                    float p1 = __expf(sacc[mi][nt][1] - nm0);
                    float p2 = __expf(sacc[mi][nt][2] - nm1);
                    float p3 = __expf(sacc[mi][nt][3] - nm1);
                    ps0 += p0 + p1; ps1 += p2 + p3;
                    float2 lo = { to_tf32(p0), to_tf32(p1) };
                    float2 hi = { to_tf32(p2), to_tf32(p3) };
                    *(float2*)&P0[8 * nt + 2 * tig] = lo;
                    *(float2*)&P1[8 * nt + 2 * tig] = hi;
                }
                ps0 += __shfl_xor_sync(0xffffffffu, ps0, 1);
                ps0 += __shfl_xor_sync(0xffffffffu, ps0, 2);
                ps1 += __shfl_xor_sync(0xffffffffu, ps1, 1);
                ps1 += __shfl_xor_sync(0xffffffffu, ps1, 2);
                ls[mi][0] = ls[mi][0] * corr0 + ps0;
                ls[mi][1] = ls[mi][1] * corr1 + ps1;
                mx[mi][0] = nm0; mx[mi][1] = nm1;
#pragma unroll
                for (int nt = 0; nt < 8; nt++) {
                    oacc[mi][nt][0] *= corr0; oacc[mi][nt][1] *= corr0;
                    oacc[mi][nt][2] *= corr1; oacc[mi][nt][3] *= corr1;
                }
            }
            __syncwarp();

#pragma unroll
            for (int s = 0; s < 8; s++) {
                float v0a[8], v1a[8];
                const float* vr0 = &V[(8 * s + tig) * KSS + 8 * g];
                const float* vr1 = &V[(8 * s + tig + 4) * KSS + 8 * g];
                *(float4*)&v0a[0] = *(const float4*)&vr0[0];
                *(float4*)&v0a[4] = *(const float4*)&vr0[4];
                *(float4*)&v1a[0] = *(const float4*)&vr1[0];
                *(float4*)&v1a[4] = *(const float4*)&vr1[4];
#pragma unroll
                for (int mi = 0; mi < 2; mi++) {
                    if (mi == 0 && !act0) continue;
                    const float* P0 = &Pw[(mi * 16 + g) * KSS + 8 * s];
                    const float* P1 = &Pw[(mi * 16 + g + 8) * KSS + 8 * s];
                    uint32_t a[4] = { __float_as_uint(P0[tig]),
                                      __float_as_uint(P1[tig]),
                                      __float_as_uint(P0[tig + 4]),
                                      __float_as_uint(P1[tig + 4]) };
#pragma unroll
                    for (int nt = 0; nt < 8; nt++) {
                        uint32_t b[2] = { __float_as_uint(v0a[nt]),
                                          __float_as_uint(v1a[nt]) };
                        mma_tf32(oacc[mi][nt], a, b);
                    }
                }
            }
            __syncwarp();
        }
    }

    int b = bh >> 4, h = bh & 15;
#pragma unroll
    for (int mi = 0; mi < 2; mi++) {
        float inv0 = 1.0f / ls[mi][0], inv1 = 1.0f / ls[mi][1];
        int row0 = trow[mi] + g;
        float* O0 = g_AO + ((size_t)(b * NS + row0)) * ND + h * HDIM;
        float* O1 = g_AO + ((size_t)(b * NS + row0 + 8)) * ND + h * HDIM;
#pragma unroll
        for (int nt = 0; nt < 8; nt++) {
            float2 lo = { to_tf32(oacc[mi][nt][0] * inv0),
                          to_tf32(oacc[mi][nt][1] * inv0) };
            float2 hi = { to_tf32(oacc[mi][nt][2] * inv1),
                          to_tf32(oacc[mi][nt][3] * inv1) };
            *(float2*)&O0[8 * nt + 2 * tig] = lo;
            *(float2*)&O1[8 * nt + 2 * tig] = hi;
        }
    }
}

// ---------------------------------------------------------------------------
extern "C" void kernel_launch(void* const* d_in, const int* in_sizes, int n_in,
                              void* d_out, int out_size)
{
    const float* x    = (const float*)d_in[0];
    const float* wq_w = (const float*)d_in[1];
    const float* wq_b = (const float*)d_in[2];
    const float* wk_w = (const float*)d_in[3];
    const float* wk_b = (const float*)d_in[4];
    const float* wv_w = (const float*)d_in[5];
    const float* wv_b = (const float*)d_in[6];
    const float* wo_w = (const float*)d_in[7];
    const float* wo_b = (const float*)d_in[8];
    float* out = (float*)d_out;

    cudaFuncSetAttribute(gemm_tf32, cudaFuncAttributeMaxDynamicSharedMemorySize,
                         GEMM_SMEM);
    cudaFuncSetAttribute(flash_attn_mma,
                         cudaFuncAttributeMaxDynamicSharedMemorySize, FLASH_SMEM);

    int prep_blocks = (int)(((size_t)NM * ND / 4 + (size_t)MM) / 256);
    prep_round<<<prep_blocks, 256>>>(x, wq_w, wk_w, wv_w, wo_w);

    gemm_tf32<<<dim3(24, NM / 128), 128, GEMM_SMEM>>>(
        wq_b, wk_b, wv_b, nullptr, 0, 1, 0);

    flash_attn_mma<<<dim3(NS / QROWS, NB * NH), 128, FLASH_SMEM>>>();

    gemm_tf32<<<dim3(8, NM / 128), 128, GEMM_SMEM>>>(
        wo_b, nullptr, nullptr, out, 1, 0, 0);
}